// round 3
// baseline (speedup 1.0000x reference)
#include <cuda_runtime.h>

#define Lf 512
#define Bf 4096
#define Tt 25
#define NP 13      // i-pairs (2*13 = 26 >= 25, slot 12 hi = pad)
#define ROW 17     // u64 row stride (odd -> conflict-free LDS.64)

__device__ float g_score[(size_t)Lf * Bf * Tt];   // viterbi max scores
__device__ float g_logz[Bf];
__device__ float g_num[Bf];

typedef unsigned long long u64;

__device__ __forceinline__ u64 pack2(float lo, float hi) {
    u64 r; asm("mov.b64 %0,{%1,%2};" : "=l"(r) : "f"(lo), "f"(hi)); return r;
}
__device__ __forceinline__ void un2(u64 v, float& a, float& b) {
    asm("mov.b64 {%0,%1},%2;" : "=f"(a), "=f"(b) : "l"(v));
}
__device__ __forceinline__ u64 fma2(u64 a, u64 b, u64 c) {
    u64 d; asm("fma.rn.f32x2 %0,%1,%2,%3;" : "=l"(d) : "l"(a), "l"(b), "l"(c)); return d;
}
__device__ __forceinline__ u64 add2(u64 a, u64 b) {
    u64 d; asm("add.rn.f32x2 %0,%1,%2;" : "=l"(d) : "l"(a), "l"(b)); return d;
}
// monotone float -> uint order map (for warp argmax via __reduce_max_sync)
__device__ __forceinline__ unsigned ford(float f) {
    unsigned v = __float_as_uint(f);
    return (v & 0x80000000u) ? ~v : (v | 0x80000000u);
}

// ---------------------------------------------------------------------------
__global__ void init_kernel(float* out, int base) {
    int i = blockIdx.x * blockDim.x + threadIdx.x;
    if (i < Bf) g_num[i] = 0.f;
    if (i == 0 && base > 0) out[0] = 0.f;
}

// ---------------------------------------------------------------------------
// Fused forward (scaled linear space, normalized by alpha[0]) + Viterbi scores.
// Block: 32 batch x 9 j-threads; each j-thread owns columns jj, jj+9, jj+18.
__global__ __launch_bounds__(288, 1) void fwd_vit_kernel(
    const float* __restrict__ em, const float* __restrict__ trans,
    const float* __restrict__ start, const float* __restrict__ endt)
{
    __shared__ u64 sA[2][32][ROW];                 // alpha pairs (a_{2p}, a_{2p+1})
    __shared__ u64 sV[2][32][ROW];                 // viterbi pairs
    __shared__ __align__(16) float sem[2][32 * Tt];

    const int tid = threadIdx.x;
    const int bi  = tid & 31;
    const int jj  = tid >> 5;          // 0..8
    const int b0  = blockIdx.x * 32;
    const int b   = b0 + bi;

    // loop-invariant transition column tables (packed over i-pairs)
    u64 Ep[3][NP], Tp[3][NP];
    float stj[3];
#pragma unroll
    for (int c = 0; c < 3; c++) {
        int j = jj + 9 * c;
        bool v = j < Tt;
        stj[c] = v ? start[j] : 0.f;
#pragma unroll
        for (int p = 0; p < NP; p++) {
            int i0 = 2 * p, i1 = 2 * p + 1;
            float t0 = (v && i0 < Tt) ? trans[i0 * Tt + j] : -1e30f;
            float t1 = (v && i1 < Tt) ? trans[i1 * Tt + j] : -1e30f;
            Tp[c][p] = pack2(t0, t1);
            Ep[c][p] = pack2((v && i0 < Tt) ? __expf(t0) : 0.f,
                             (v && i1 < Tt) ? __expf(t1) : 0.f);
        }
    }

    // stage em[0]
    if (tid < 200)
        ((float4*)sem[0])[tid] = ((const float4*)(em + (size_t)b0 * Tt))[tid];
    __syncthreads();

    // ---- l = 0 ----
    {
        float* fa = (float*)&sA[0][bi][0];
        float* fv = (float*)&sV[0][bi][0];
#pragma unroll
        for (int c = 0; c < 3; c++) {
            int j = jj + 9 * c;
            if (j < Tt) {
                float e = sem[0][bi * Tt + j];
                float s = stj[c] + e;
                fa[j] = __expf(s);
                fv[j] = s;
                g_score[(size_t)b * Tt + j] = s;
            }
        }
        if (jj == 0) {   // pads (float index 25) in both buffers
            ((float*)&sA[0][bi][0])[25] = 0.f;   ((float*)&sV[0][bi][0])[25] = -1e30f;
            ((float*)&sA[1][bi][0])[25] = 0.f;   ((float*)&sV[1][bi][0])[25] = -1e30f;
        }
    }
    if (tid < 200)
        ((float4*)sem[1])[tid] = ((const float4*)(em + ((size_t)Bf + b0) * Tt))[tid];
    __syncthreads();

    float logacc = 0.f;

    for (int l = 1; l < Lf; l++) {
        const int rp = (l - 1) & 1, wp = l & 1;

        // stage em[l+1] into the buffer whose reads finished last step
        if (l < Lf - 1 && tid < 200)
            ((float4*)sem[rp])[tid] =
                ((const float4*)(em + ((size_t)(l + 1) * Bf + b0) * Tt))[tid];

        const u64* pa = &sA[rp][bi][0];
        const u64* pv = &sV[rp][bi][0];
        u64 r0 = 0ull, r1 = 0ull, r2 = 0ull;     // packed (0.f,0.f)
        float m0 = -1e30f, m1 = -1e30f, m2 = -1e30f;
        float la = 0.f;
#pragma unroll
        for (int p = 0; p < NP; p++) {
            u64 av = pa[p];
            u64 vv = pv[p];
            if (p == 0) { float a0, a1; un2(av, a0, a1); la = __logf(a0); }
            r0 = fma2(av, Ep[0][p], r0);
            r1 = fma2(av, Ep[1][p], r1);
            r2 = fma2(av, Ep[2][p], r2);
            float sx, sy;
            un2(add2(vv, Tp[0][p]), sx, sy); m0 = fmaxf(fmaxf(m0, sx), sy);
            un2(add2(vv, Tp[1][p]), sx, sy); m1 = fmaxf(fmaxf(m1, sx), sy);
            un2(add2(vv, Tp[2][p]), sx, sy); m2 = fmaxf(fmaxf(m2, sx), sy);
        }
        logacc += la;

        float* fa = (float*)&sA[wp][bi][0];
        float* fv = (float*)&sV[wp][bi][0];
        u64   rr[3] = { r0, r1, r2 };
        float mm[3] = { m0, m1, m2 };
#pragma unroll
        for (int c = 0; c < 3; c++) {
            int j = jj + 9 * c;
            if (j < Tt) {
                float e = sem[wp][bi * Tt + j];
                float x, y; un2(rr[c], x, y);
                float u = (x + y) * __expf(e - la);
                float s = mm[c] + e;       // == max_i((v+T)+e): monotone add
                fa[j] = u;
                fv[j] = s;
                g_score[((size_t)l * Bf + b) * Tt + j] = s;
            }
        }
        __syncthreads();
    }

    // logz = sum log(scale) + log( sum_j a_final[j] * exp(end[j]) )
    if (jj == 0) {
        const u64* pa = &sA[(Lf - 1) & 1][bi][0];
        float dot = 0.f;
#pragma unroll
        for (int p = 0; p < NP; p++) {
            float x, y; un2(pa[p], x, y);
            int i0 = 2 * p, i1 = 2 * p + 1;
            dot += x * __expf(endt[i0]);
            if (i1 < Tt) dot += y * __expf(endt[i1]);
        }
        g_logz[b] = logacc + __logf(dot);
    }
}

// ---------------------------------------------------------------------------
// Gold-path numerator: parallel over (batch, 16-step chunks).
__global__ void numer_kernel(const float* __restrict__ em, const int* __restrict__ tags,
                             const float* __restrict__ trans, const float* __restrict__ start,
                             const float* __restrict__ endt)
{
    int idx = blockIdx.x * blockDim.x + threadIdx.x;
    if (idx >= Bf * 32) return;
    int b  = idx & (Bf - 1);
    int c  = idx >> 12;
    int l0 = c * 16;
    float acc = 0.f;
    int prev = 0;
    if (c > 0) prev = tags[(size_t)(l0 - 1) * Bf + b];
#pragma unroll
    for (int dl = 0; dl < 16; dl++) {
        int l  = l0 + dl;
        int tg = tags[(size_t)l * Bf + b];
        acc += em[((size_t)l * Bf + b) * Tt + tg];
        if (l == 0) acc += start[tg];
        else        acc += trans[prev * Tt + tg];
        prev = tg;
    }
    if (l0 + 16 == Lf) acc += endt[prev];
    atomicAdd(&g_num[b], acc);
}

// ---------------------------------------------------------------------------
// Backtrack: one warp per batch element. Argmax via monotone-uint reduce_max +
// ballot (first-max = lowest lane, matching jnp.argmax). Loads prefetched.
__global__ __launch_bounds__(256) void backtrack_kernel(
    const float* __restrict__ em, const float* __restrict__ trans,
    const float* __restrict__ endt, float* __restrict__ out, int base)
{
    __shared__ float st[Tt * Tt];
    __shared__ float cpart[8];
    const int tid = threadIdx.x;
    for (int i = tid; i < Tt * Tt; i += 256) st[i] = trans[i];
    __syncthreads();

    const int b    = (blockIdx.x * 256 + tid) >> 5;
    const int lane = tid & 31;
    const bool alive = lane < Tt;

    // last tag = argmax_j(score[L-1][b][j] + end[j])
    float sc = alive ? g_score[((size_t)(Lf - 1) * Bf + b) * Tt + lane] : -3e38f;
    float t  = alive ? sc + endt[lane] : -3e38f;
    unsigned u  = ford(t);
    unsigned um = __reduce_max_sync(0xffffffffu, u);
    int jn = __ffs(__ballot_sync(0xffffffffu, u == um)) - 1;
    if (lane == 0) out[base + (size_t)(Lf - 1) * Bf + b] = (float)jn;

    // prefetch for l = Lf-2 (addresses independent of jn)
    float scn = alive ? g_score[((size_t)(Lf - 2) * Bf + b) * Tt + lane] : 0.f;
    float en  = alive ? em[((size_t)(Lf - 1) * Bf + b) * Tt + lane] : 0.f;

    for (int l = Lf - 2; l >= 0; l--) {
        float s = scn, e = en;
        if (l > 0) {
            scn = alive ? g_score[((size_t)(l - 1) * Bf + b) * Tt + lane] : 0.f;
            en  = alive ? em[((size_t)l * Bf + b) * Tt + lane] : 0.f;
        }
        float ej = __shfl_sync(0xffffffffu, e, jn);               // em[l+1][b][jn]
        float tt = alive ? (s + st[lane * Tt + jn]) + ej : -3e38f; // exact ref order
        unsigned uu = ford(tt);
        unsigned m2 = __reduce_max_sync(0xffffffffu, uu);
        jn = __ffs(__ballot_sync(0xffffffffu, uu == m2)) - 1;
        if (lane == 0) out[base + (size_t)l * Bf + b] = (float)jn;
    }

    // nll: block-reduce (logz - num)/B, one atomic per block
    float c = 0.f;
    if (lane == 0 && base > 0) c = (g_logz[b] - g_num[b]) * (1.0f / Bf);
    if (lane == 0) cpart[tid >> 5] = c;
    __syncthreads();
    if (tid == 0 && base > 0) {
        float sum = 0.f;
#pragma unroll
        for (int w = 0; w < 8; w++) sum += cpart[w];
        atomicAdd(out, sum);
    }
}

// ---------------------------------------------------------------------------
extern "C" void kernel_launch(void* const* d_in, const int* in_sizes, int n_in,
                              void* d_out, int out_size) {
    const float* em    = (const float*)d_in[0];
    const int*   tags  = (const int*)d_in[1];
    const float* trans = (const float*)d_in[2];
    const float* start = (const float*)d_in[3];
    const float* endt  = (const float*)d_in[4];
    float* out = (float*)d_out;

    int base = out_size - Lf * Bf;   // expected 1 (out[0] = nll)
    if (base < 0) base = 0;

    init_kernel<<<16, 256>>>(out, base);
    fwd_vit_kernel<<<Bf / 32, 288>>>(em, trans, start, endt);
    numer_kernel<<<(Bf * 32) / 256, 256>>>(em, tags, trans, start, endt);
    backtrack_kernel<<<(Bf * 32) / 256, 256>>>(em, trans, endt, out, base);
}

// round 4
// speedup vs baseline: 1.2341x; 1.2341x over previous
#include <cuda_runtime.h>

#define Lf 512
#define Bf 4096
#define Tt 25
#define NP 13      // i-pairs: (2p, 2p+1), p=12 high half = pad (i=25)
#define GST 26     // g_score row stride (even -> STG.64 aligned)

__device__ float g_score[(size_t)Lf * Bf * GST];   // viterbi max scores (+pad col)
__device__ float g_logz[Bf];
__device__ float g_num[Bf];

typedef unsigned long long u64;

__device__ __forceinline__ u64 pack2(float lo, float hi) {
    u64 r; asm("mov.b64 %0,{%1,%2};" : "=l"(r) : "f"(lo), "f"(hi)); return r;
}
__device__ __forceinline__ void un2(u64 v, float& a, float& b) {
    asm("mov.b64 {%0,%1},%2;" : "=f"(a), "=f"(b) : "l"(v));
}
__device__ __forceinline__ u64 fma2(u64 a, u64 b, u64 c) {
    u64 d; asm("fma.rn.f32x2 %0,%1,%2,%3;" : "=l"(d) : "l"(a), "l"(b), "l"(c)); return d;
}
__device__ __forceinline__ u64 add2(u64 a, u64 b) {
    u64 d; asm("add.rn.f32x2 %0,%1,%2;" : "=l"(d) : "l"(a), "l"(b)); return d;
}
// monotone float -> uint order map (warp argmax via __reduce_max_sync)
__device__ __forceinline__ unsigned ford(float f) {
    unsigned v = __float_as_uint(f);
    return (v & 0x80000000u) ? ~v : (v | 0x80000000u);
}

// ---------------------------------------------------------------------------
__global__ void init_kernel(float* out, int base) {
    int i = blockIdx.x * blockDim.x + threadIdx.x;
    if (i < Bf) g_num[i] = 0.f;
    if (i == 0 && base > 0) out[0] = 0.f;
}

// ---------------------------------------------------------------------------
// Fused forward (scaled linear space, normalized by alpha[0]) + Viterbi scores.
// Block: 32 batch (lane) x 13 j-warps; warp jj owns adjacent columns 2jj, 2jj+1.
// State in smem as ulonglong2 { (a_{2p},a_{2p+1}), (v_{2p},v_{2p+1}) } -> LDS.128.
__global__ __launch_bounds__(416, 1) void fwd_vit_kernel(
    const float* __restrict__ em, const float* __restrict__ trans,
    const float* __restrict__ start, const float* __restrict__ endt)
{
    __shared__ ulonglong2 sS[2][32][NP];                 // 13312 B
    __shared__ __align__(16) float sem[2][32 * Tt];      // 6400 B

    const int tid = threadIdx.x;
    const int bi  = tid & 31;
    const int jj  = tid >> 5;            // 0..12 (warp id)
    const int j0  = 2 * jj;
    const int j1  = j0 + 1;
    const bool hasJ1 = (j1 < Tt);        // false only for jj==12
    const int b0  = blockIdx.x * 32;
    const int b   = b0 + bi;

    // loop-invariant transition tables (i-pairs x 2 adjacent columns)
    u64 Ep0[NP], Ep1[NP], Tp0[NP], Tp1[NP];
#pragma unroll
    for (int p = 0; p < NP; p++) {
        const int i0 = 2 * p, i1 = 2 * p + 1;
        const bool hi = (i1 < Tt);                        // false only p==12
        float t00 = trans[i0 * Tt + j0];
        float t01 = hi ? trans[i1 * Tt + j0] : -1e30f;
        Tp0[p] = pack2(t00, t01);
        Ep0[p] = pack2(__expf(t00), hi ? __expf(t01) : 0.f);
        float t10 = hasJ1 ? trans[i0 * Tt + j1] : -1e30f;
        float t11 = (hasJ1 && hi) ? trans[i1 * Tt + j1] : -1e30f;
        Tp1[p] = pack2(t10, t11);
        Ep1[p] = pack2(hasJ1 ? __expf(t10) : 0.f,
                       (hasJ1 && hi) ? __expf(t11) : 0.f);
    }
    const float st0 = start[j0];
    const float st1 = hasJ1 ? start[j1] : 0.f;

    // stage em[0]
    if (tid < 200)
        ((float4*)sem[0])[tid] = ((const float4*)(em + (size_t)b0 * Tt))[tid];
    __syncthreads();

    // ---- l = 0 ----
    {
        float e0 = sem[0][bi * Tt + j0];
        float e1 = hasJ1 ? sem[0][bi * Tt + j1] : 0.f;
        float s0 = st0 + e0;
        float s1 = hasJ1 ? (st1 + e1) : -1e30f;
        float a0 = __expf(s0);
        float a1 = hasJ1 ? __expf(s1) : 0.f;
        ulonglong2 w; w.x = pack2(a0, a1); w.y = pack2(s0, s1);
        sS[0][bi][jj] = w;
        *(float2*)&g_score[(size_t)b * GST + j0] = make_float2(s0, s1);
    }
    if (tid < 200)
        ((float4*)sem[1])[tid] = ((const float4*)(em + ((size_t)Bf + b0) * Tt))[tid];
    __syncthreads();

    float logacc = 0.f;
    float* gsp = &g_score[((size_t)Bf + b) * GST + j0];        // l=1 slot
    const float4* emstage = (const float4*)(em + ((size_t)2 * Bf + b0) * Tt);

    for (int l = 1; l < Lf; l++) {
        const int rp = (l - 1) & 1, wp = l & 1;

        // stage em[l+1] into sem[(l+1)&1] == sem[rp]
        if (l < Lf - 1 && tid < 200)
            ((float4*)sem[rp])[tid] = emstage[tid];

        const ulonglong2* ps = &sS[rp][bi][0];
        u64 r0 = 0ull, r1 = 0ull;
        float m0 = -1e30f, m1 = -1e30f;
        float a00 = 0.f;
#pragma unroll
        for (int p = 0; p < NP; p++) {
            ulonglong2 s2 = ps[p];                 // LDS.128, conflict-free
            u64 av = s2.x, vv = s2.y;
            if (p == 0) { float h; un2(av, a00, h); }
            r0 = fma2(av, Ep0[p], r0);
            r1 = fma2(av, Ep1[p], r1);
            float x, y;
            un2(add2(vv, Tp0[p]), x, y); m0 = fmaxf(m0, fmaxf(x, y));
            un2(add2(vv, Tp1[p]), x, y); m1 = fmaxf(m1, fmaxf(x, y));
        }
        const float la = __logf(a00);
        logacc += la;

        float e0 = sem[wp][bi * Tt + j0];
        float e1 = hasJ1 ? sem[wp][bi * Tt + j1] : 0.f;
        float x, y;
        un2(r0, x, y); float u0 = (x + y) * __expf(e0 - la);
        un2(r1, x, y); float u1 = hasJ1 ? (x + y) * __expf(e1 - la) : 0.f;
        float s0 = m0 + e0;                              // == max_i((v+T)+e) exactly
        float s1 = hasJ1 ? (m1 + e1) : -1e30f;

        ulonglong2 w; w.x = pack2(u0, u1); w.y = pack2(s0, s1);
        sS[wp][bi][jj] = w;
        *(float2*)gsp = make_float2(s0, s1);
        gsp += (size_t)Bf * GST;
        emstage += (size_t)(Bf * Tt) / 4;
        __syncthreads();
    }

    // logz = sum log(scale) + log( sum_i B_final[i] * exp(end[i]) )
    if (jj == 0) {
        const ulonglong2* ps = &sS[(Lf - 1) & 1][bi][0];
        float dot = 0.f;
#pragma unroll
        for (int p = 0; p < NP; p++) {
            float x, y; un2(ps[p].x, x, y);
            dot += x * __expf(endt[2 * p]);
            if (2 * p + 1 < Tt) dot += y * __expf(endt[2 * p + 1]);
        }
        g_logz[b] = logacc + __logf(dot);
    }
}

// ---------------------------------------------------------------------------
// Gold-path numerator: parallel over (batch, 16-step chunks).
__global__ void numer_kernel(const float* __restrict__ em, const int* __restrict__ tags,
                             const float* __restrict__ trans, const float* __restrict__ start,
                             const float* __restrict__ endt)
{
    int idx = blockIdx.x * blockDim.x + threadIdx.x;
    if (idx >= Bf * 32) return;
    int b  = idx & (Bf - 1);
    int c  = idx >> 12;
    int l0 = c * 16;
    float acc = 0.f;
    int prev = 0;
    if (c > 0) prev = tags[(size_t)(l0 - 1) * Bf + b];
#pragma unroll
    for (int dl = 0; dl < 16; dl++) {
        int l  = l0 + dl;
        int tg = tags[(size_t)l * Bf + b];
        acc += em[((size_t)l * Bf + b) * Tt + tg];
        if (l == 0) acc += start[tg];
        else        acc += trans[prev * Tt + tg];
        prev = tg;
    }
    if (l0 + 16 == Lf) acc += endt[prev];
    atomicAdd(&g_num[b], acc);
}

// ---------------------------------------------------------------------------
// Backtrack: one warp per batch element, 3-deep prefetch (addresses are
// jn-independent). Argmax = reduce_max(ford) + ballot (first-max = lowest
// lane, matching jnp.argmax), candidates computed exactly as reference:
// ((score + trans) + em_next).
__global__ __launch_bounds__(256) void backtrack_kernel(
    const float* __restrict__ em, const float* __restrict__ trans,
    const float* __restrict__ endt, float* __restrict__ out, int base)
{
    __shared__ float st[Tt * Tt];
    __shared__ float cpart[8];
    const int tid = threadIdx.x;
    for (int i = tid; i < Tt * Tt; i += 256) st[i] = trans[i];
    __syncthreads();

    const int b    = (blockIdx.x * 256 + tid) >> 5;
    const int lane = tid & 31;
    const bool alive = lane < Tt;

    // last tag = argmax_j(score[L-1][b][j] + end[j])
    float sc = alive ? g_score[((size_t)(Lf - 1) * Bf + b) * GST + lane] : -3e38f;
    float t  = alive ? sc + endt[lane] : -3e38f;
    unsigned u  = ford(t);
    unsigned um = __reduce_max_sync(0xffffffffu, u);
    int jn = __ffs(__ballot_sync(0xffffffffu, u == um)) - 1;
    if (lane == 0) out[base + (size_t)(Lf - 1) * Bf + b] = (float)jn;

    // prefetch ring (depth 3): iteration l needs score[l], em[l+1]
    float sb[3], eb[3];
#pragma unroll
    for (int k = 0; k < 3; k++) {
        int l = Lf - 2 - k;
        sb[k] = alive ? g_score[((size_t)l * Bf + b) * GST + lane] : 0.f;
        eb[k] = alive ? em[((size_t)(l + 1) * Bf + b) * Tt + lane] : 0.f;
    }
    const float* sp  = &g_score[((size_t)(Lf - 5) * Bf + b) * GST + lane];
    const float* epp = &em[((size_t)(Lf - 4) * Bf + b) * Tt + lane];
    int k = 0;

    for (int l = Lf - 2; l >= 0; l--) {
        float s = sb[k], e = eb[k];
        if (l >= 3) {
            sb[k] = alive ? *sp  : 0.f;
            eb[k] = alive ? *epp : 0.f;
            sp  -= (size_t)Bf * GST;
            epp -= (size_t)Bf * Tt;
        }
        float ej = __shfl_sync(0xffffffffu, e, jn);               // em[l+1][b][jn]
        float tt = alive ? (s + st[lane * Tt + jn]) + ej : -3e38f;
        unsigned uu = ford(tt);
        unsigned m2 = __reduce_max_sync(0xffffffffu, uu);
        jn = __ffs(__ballot_sync(0xffffffffu, uu == m2)) - 1;
        if (lane == 0) out[base + (size_t)l * Bf + b] = (float)jn;
        if (++k == 3) k = 0;
    }

    // nll: block-reduce (logz - num)/B, one atomic per block
    float c = 0.f;
    if (lane == 0 && base > 0) c = (g_logz[b] - g_num[b]) * (1.0f / Bf);
    if (lane == 0) cpart[tid >> 5] = c;
    __syncthreads();
    if (tid == 0 && base > 0) {
        float sum = 0.f;
#pragma unroll
        for (int w = 0; w < 8; w++) sum += cpart[w];
        atomicAdd(out, sum);
    }
}

// ---------------------------------------------------------------------------
extern "C" void kernel_launch(void* const* d_in, const int* in_sizes, int n_in,
                              void* d_out, int out_size) {
    const float* em    = (const float*)d_in[0];
    const int*   tags  = (const int*)d_in[1];
    const float* trans = (const float*)d_in[2];
    const float* start = (const float*)d_in[3];
    const float* endt  = (const float*)d_in[4];
    float* out = (float*)d_out;

    int base = out_size - Lf * Bf;   // expected 1 (out[0] = nll)
    if (base < 0) base = 0;

    init_kernel<<<16, 256>>>(out, base);
    fwd_vit_kernel<<<Bf / 32, 416>>>(em, trans, start, endt);
    numer_kernel<<<(Bf * 32) / 256, 256>>>(em, tags, trans, start, endt);
    backtrack_kernel<<<(Bf * 32) / 256, 256>>>(em, trans, endt, out, base);
}

// round 5
// speedup vs baseline: 1.6109x; 1.3053x over previous
#include <cuda_runtime.h>

#define Lf 512
#define Bf 4096
#define Tt 25
#define NP 13      // i-pairs: (2p, 2p+1), p=12 high half = pad
#define GST 26     // g_score row stride (even -> STG.64 aligned)

__device__ float g_score[(size_t)Lf * Bf * GST];
__device__ float g_logz[Bf];
__device__ float g_num[Bf];

typedef unsigned long long u64;

__device__ __forceinline__ u64 pack2(float lo, float hi) {
    u64 r; asm("mov.b64 %0,{%1,%2};" : "=l"(r) : "f"(lo), "f"(hi)); return r;
}
__device__ __forceinline__ void un2(u64 v, float& a, float& b) {
    asm("mov.b64 {%0,%1},%2;" : "=f"(a), "=f"(b) : "l"(v));
}
__device__ __forceinline__ u64 fma2(u64 a, u64 b, u64 c) {
    u64 d; asm("fma.rn.f32x2 %0,%1,%2,%3;" : "=l"(d) : "l"(a), "l"(b), "l"(c)); return d;
}
__device__ __forceinline__ u64 add2(u64 a, u64 b) {
    u64 d; asm("add.rn.f32x2 %0,%1,%2;" : "=l"(d) : "l"(a), "l"(b)); return d;
}
__device__ __forceinline__ unsigned ford(float f) {
    unsigned v = __float_as_uint(f);
    return (v & 0x80000000u) ? ~v : (v | 0x80000000u);
}

// ---------------------------------------------------------------------------
__global__ void init_kernel(float* out, int base) {
    int i = blockIdx.x * blockDim.x + threadIdx.x;
    if (i < Bf) g_num[i] = 0.f;
    if (i == 0 && base > 0) out[0] = 0.f;
}

// ---------------------------------------------------------------------------
// Fused forward (scaled linear, normalized by alpha[0]) + Viterbi scores.
// 32 batch x 13 j-warps; warp jj owns columns 2jj, 2jj+1.
// Emission staging software-pipelined: LDG 2 iterations ahead into register
// payloads, STS 1 iteration ahead into a 3-phase smem ring.
__global__ __launch_bounds__(416) void fwd_vit_kernel(
    const float* __restrict__ em, const float* __restrict__ trans,
    const float* __restrict__ start, const float* __restrict__ endt)
{
    __shared__ ulonglong2 sS[2][32][NP];
    __shared__ __align__(16) float sem[3][32 * Tt];

    const int tid = threadIdx.x;
    const int bi  = tid & 31;
    const int jj  = tid >> 5;            // 0..12
    const int j0  = 2 * jj;
    const int j1  = j0 + 1;
    const bool hasJ1 = (j1 < Tt);
    const int b0  = blockIdx.x * 32;
    const int b   = b0 + bi;
    const bool stager = (tid < 200);     // 200*4 = 800 = 32*25 floats

    // loop-invariant transition tables
    u64 Ep0[NP], Ep1[NP], Tp0[NP], Tp1[NP];
#pragma unroll
    for (int p = 0; p < NP; p++) {
        const int i0 = 2 * p, i1 = 2 * p + 1;
        const bool hi = (i1 < Tt);
        float t00 = trans[i0 * Tt + j0];
        float t01 = hi ? trans[i1 * Tt + j0] : -1e30f;
        Tp0[p] = pack2(t00, t01);
        Ep0[p] = pack2(__expf(t00), hi ? __expf(t01) : 0.f);
        float t10 = hasJ1 ? trans[i0 * Tt + j1] : -1e30f;
        float t11 = (hasJ1 && hi) ? trans[i1 * Tt + j1] : -1e30f;
        Tp1[p] = pack2(t10, t11);
        Ep1[p] = pack2(hasJ1 ? __expf(t10) : 0.f,
                       (hasJ1 && hi) ? __expf(t11) : 0.f);
    }
    const float st0 = start[j0];
    const float st1 = hasJ1 ? start[j1] : 0.f;

    // prologue staging: em[0] -> sem[0], em[1] -> sem[1]; LDG em[2]->P0, em[3]->P1
    float4 P0, P1;
    if (stager) {
        const float4* e0p = (const float4*)(em + (size_t)b0 * Tt);
        const size_t step4 = (size_t)Bf * Tt / 4;
        ((float4*)sem[0])[tid] = e0p[tid];
        ((float4*)sem[1])[tid] = e0p[tid + step4];
        P0 = e0p[tid + 2 * step4];
        P1 = e0p[tid + 3 * step4];
    }
    __syncthreads();

    // ---- l = 0 ----
    {
        float e0 = sem[0][bi * Tt + j0];
        float e1 = hasJ1 ? sem[0][bi * Tt + j1] : 0.f;
        float s0 = st0 + e0;
        float s1 = hasJ1 ? (st1 + e1) : -1e30f;
        ulonglong2 w;
        w.x = pack2(__expf(s0), hasJ1 ? __expf(s1) : 0.f);
        w.y = pack2(s0, s1);
        sS[0][bi][jj] = w;
        *(float2*)&g_score[(size_t)b * GST + j0] = make_float2(s0, s1);
    }
    __syncthreads();

    float logacc = 0.f;
    float* gsp = &g_score[((size_t)Bf + b) * GST + j0];

    for (int l = 1; l < Lf; l++) {
        const int rp = (l - 1) & 1, wp = l & 1;

        // pipeline: STS payload holding em[l+1]; reload it with em[l+3]
        if (stager) {
            float4 Q = ((l & 1) == 0) ? P1 : P0;   // P[(l+1)&1]
            if (l < Lf - 1)
                ((float4*)sem[(l + 1) % 3])[tid] = Q;
            if (l <= Lf - 4) {
                float4 R = ((const float4*)(em + ((size_t)(l + 3) * Bf + b0) * Tt))[tid];
                if ((l & 1) == 0) P1 = R; else P0 = R;
            }
        }

        const ulonglong2* ps = &sS[rp][bi][0];
        u64 r0 = 0ull, r1 = 0ull;
        float m0 = -1e30f, m1 = -1e30f;
        float a00 = 0.f;
#pragma unroll
        for (int p = 0; p < NP; p++) {
            ulonglong2 s2 = ps[p];                 // LDS.128 conflict-free
            u64 av = s2.x, vv = s2.y;
            if (p == 0) { float h; un2(av, a00, h); }
            r0 = fma2(av, Ep0[p], r0);
            r1 = fma2(av, Ep1[p], r1);
            float x, y;
            un2(add2(vv, Tp0[p]), x, y); m0 = fmaxf(m0, fmaxf(x, y));
            un2(add2(vv, Tp1[p]), x, y); m1 = fmaxf(m1, fmaxf(x, y));
        }
        const float la = __logf(a00);
        logacc += la;

        float e0 = sem[l % 3][bi * Tt + j0];
        float e1 = hasJ1 ? sem[l % 3][bi * Tt + j1] : 0.f;
        float x, y;
        un2(r0, x, y); float u0 = (x + y) * __expf(e0 - la);
        un2(r1, x, y); float u1 = hasJ1 ? (x + y) * __expf(e1 - la) : 0.f;
        float s0 = m0 + e0;                 // == max_i((v+T)+e) exactly (monotone)
        float s1 = hasJ1 ? (m1 + e1) : -1e30f;

        ulonglong2 w; w.x = pack2(u0, u1); w.y = pack2(s0, s1);
        sS[wp][bi][jj] = w;
        *(float2*)gsp = make_float2(s0, s1);
        gsp += (size_t)Bf * GST;
        __syncthreads();
    }

    if (jj == 0) {
        const ulonglong2* ps = &sS[(Lf - 1) & 1][bi][0];
        float dot = 0.f;
#pragma unroll
        for (int p = 0; p < NP; p++) {
            float x, y; un2(ps[p].x, x, y);
            dot += x * __expf(endt[2 * p]);
            if (2 * p + 1 < Tt) dot += y * __expf(endt[2 * p + 1]);
        }
        g_logz[b] = logacc + __logf(dot);
    }
}

// ---------------------------------------------------------------------------
__global__ void numer_kernel(const float* __restrict__ em, const int* __restrict__ tags,
                             const float* __restrict__ trans, const float* __restrict__ start,
                             const float* __restrict__ endt)
{
    int idx = blockIdx.x * blockDim.x + threadIdx.x;
    if (idx >= Bf * 32) return;
    int b  = idx & (Bf - 1);
    int c  = idx >> 12;
    int l0 = c * 16;
    float acc = 0.f;
    int prev = 0;
    if (c > 0) prev = tags[(size_t)(l0 - 1) * Bf + b];
#pragma unroll
    for (int dl = 0; dl < 16; dl++) {
        int l  = l0 + dl;
        int tg = tags[(size_t)l * Bf + b];
        acc += em[((size_t)l * Bf + b) * Tt + tg];
        if (l == 0) acc += start[tg];
        else        acc += trans[prev * Tt + tg];
        prev = tg;
    }
    if (l0 + 16 == Lf) acc += endt[prev];
    atomicAdd(&g_num[b], acc);
}

// ---------------------------------------------------------------------------
// Backtrack group body: processes 8 steps (lbase down to lbase-7) using
// CONSTANT-INDEX register arrays; prefetches the next group's 16 loads.
__device__ __forceinline__ void bt_group(
    const float* __restrict__ em, const float* st, float* out, int base,
    int b, int lane, bool alive, int lbase, int& jn,
    float (&cs)[8], float (&ce)[8], float (&ns)[8], float (&ne)[8], bool load_next)
{
    if (load_next) {
#pragma unroll
        for (int k = 0; k < 8; k++) {
            int l = lbase - 8 - k;
            bool ok = alive && (l >= 0);
            ns[k] = ok ? g_score[((size_t)l * Bf + b) * GST + lane] : 0.f;
            ne[k] = ok ? em[((size_t)(l + 1) * Bf + b) * Tt + lane] : 0.f;
        }
    }
#pragma unroll
    for (int k = 0; k < 8; k++) {
        int l = lbase - k;
        float ej = __shfl_sync(0xffffffffu, ce[k], jn);
        float tt = alive ? (cs[k] + st[lane * Tt + jn]) + ej : -3e38f;
        unsigned uu = ford(tt);
        unsigned mx = __reduce_max_sync(0xffffffffu, uu);
        int j2 = __ffs(__ballot_sync(0xffffffffu, uu == mx)) - 1;
        if (l >= 0) {
            jn = j2;
            if (lane == 0) out[base + (size_t)l * Bf + b] = (float)jn;
        }
    }
}

__global__ __launch_bounds__(256) void backtrack_kernel(
    const float* __restrict__ em, const float* __restrict__ trans,
    const float* __restrict__ endt, float* __restrict__ out, int base)
{
    __shared__ float st[Tt * Tt];
    __shared__ float cpart[8];
    const int tid = threadIdx.x;
    for (int i = tid; i < Tt * Tt; i += 256) st[i] = trans[i];
    __syncthreads();

    const int b    = (blockIdx.x * 256 + tid) >> 5;
    const int lane = tid & 31;
    const bool alive = lane < Tt;

    // last tag
    float sc = alive ? g_score[((size_t)(Lf - 1) * Bf + b) * GST + lane] : -3e38f;
    float t  = alive ? sc + endt[lane] : -3e38f;
    unsigned u  = ford(t);
    unsigned um = __reduce_max_sync(0xffffffffu, u);
    int jn = __ffs(__ballot_sync(0xffffffffu, u == um)) - 1;
    if (lane == 0) out[base + (size_t)(Lf - 1) * Bf + b] = (float)jn;

    // 512 padded iterations (l = 510 .. -1) in 64 groups of 8, ping-pong regs
    float sA[8], eA[8], sB[8], eB[8];
#pragma unroll
    for (int k = 0; k < 8; k++) {
        int l = Lf - 2 - k;
        sA[k] = alive ? g_score[((size_t)l * Bf + b) * GST + lane] : 0.f;
        eA[k] = alive ? em[((size_t)(l + 1) * Bf + b) * Tt + lane] : 0.f;
    }
    for (int g = 0; g < 64; g += 2) {
        bt_group(em, st, out, base, b, lane, alive, Lf - 2 - 8 * g, jn,
                 sA, eA, sB, eB, true);
        bt_group(em, st, out, base, b, lane, alive, Lf - 2 - 8 * (g + 1), jn,
                 sB, eB, sA, eA, g + 1 < 63);
    }

    // nll: block-reduce (logz - num)/B
    float c = 0.f;
    if (lane == 0 && base > 0) c = (g_logz[b] - g_num[b]) * (1.0f / Bf);
    if (lane == 0) cpart[tid >> 5] = c;
    __syncthreads();
    if (tid == 0 && base > 0) {
        float sum = 0.f;
#pragma unroll
        for (int w = 0; w < 8; w++) sum += cpart[w];
        atomicAdd(out, sum);
    }
}

// ---------------------------------------------------------------------------
extern "C" void kernel_launch(void* const* d_in, const int* in_sizes, int n_in,
                              void* d_out, int out_size) {
    const float* em    = (const float*)d_in[0];
    const int*   tags  = (const int*)d_in[1];
    const float* trans = (const float*)d_in[2];
    const float* start = (const float*)d_in[3];
    const float* endt  = (const float*)d_in[4];
    float* out = (float*)d_out;

    int base = out_size - Lf * Bf;
    if (base < 0) base = 0;

    init_kernel<<<16, 256>>>(out, base);
    fwd_vit_kernel<<<Bf / 32, 416>>>(em, trans, start, endt);
    numer_kernel<<<(Bf * 32) / 256, 256>>>(em, tags, trans, start, endt);
    backtrack_kernel<<<(Bf * 32) / 256, 256>>>(em, trans, endt, out, base);
}

// round 6
// speedup vs baseline: 1.8912x; 1.1740x over previous
#include <cuda_runtime.h>

#define Lf 512
#define Bf 4096
#define Tt 25
#define NP 13      // i-pairs (2p, 2p+1); p=12 hi half = pad lane 25
#define GST 32     // g_score row stride (128B-aligned rows)

__device__ float g_score[(size_t)Lf * Bf * GST];
__device__ float g_logz[Bf];
__device__ float g_num[Bf];

typedef unsigned long long u64;

__device__ __forceinline__ u64 pack2(float lo, float hi) {
    u64 r; asm("mov.b64 %0,{%1,%2};" : "=l"(r) : "f"(lo), "f"(hi)); return r;
}
__device__ __forceinline__ void un2(u64 v, float& a, float& b) {
    asm("mov.b64 {%0,%1},%2;" : "=f"(a), "=f"(b) : "l"(v));
}
__device__ __forceinline__ u64 fma2(u64 a, u64 b, u64 c) {
    u64 d; asm("fma.rn.f32x2 %0,%1,%2,%3;" : "=l"(d) : "l"(a), "l"(b), "l"(c)); return d;
}
__device__ __forceinline__ u64 add2(u64 a, u64 b) {
    u64 d; asm("add.rn.f32x2 %0,%1,%2;" : "=l"(d) : "l"(a), "l"(b)); return d;
}
__device__ __forceinline__ unsigned ford(float f) {
    unsigned v = __float_as_uint(f);
    return (v & 0x80000000u) ? ~v : (v | 0x80000000u);
}

// ---------------------------------------------------------------------------
__global__ void init_kernel(float* out, int base) {
    int i = blockIdx.x * blockDim.x + threadIdx.x;
    if (i < Bf) g_num[i] = 0.f;
    if (i == 0 && base > 0) out[0] = 0.f;
}

// ---------------------------------------------------------------------------
// Warp-per-chain fused forward + Viterbi. Lane j owns tag column j.
// No shared memory, no barriers: state broadcast via warp shuffles.
// Forward in scaled linear space (normalized each step by previous alpha[0]).
__global__ __launch_bounds__(256, 3) void fwd_vit_kernel(
    const float* __restrict__ em, const float* __restrict__ trans,
    const float* __restrict__ start, const float* __restrict__ endt)
{
    const int lane = threadIdx.x & 31;
    const int b    = (blockIdx.x * blockDim.x + threadIdx.x) >> 5;  // 0..Bf-1
    const bool act = lane < Tt;
    const int  j   = act ? lane : 0;          // clamp for safe table loads

    // loop-invariant tables: column j of exp(trans) and trans, packed over i-pairs
    u64 Ep[NP], Tp[NP];
#pragma unroll
    for (int p = 0; p < NP; p++) {
        const int i0 = 2 * p, i1 = 2 * p + 1;
        float t0 = trans[i0 * Tt + j];
        float t1 = (i1 < Tt) ? trans[i1 * Tt + j] : -1e30f;
        Tp[p] = pack2(t0, t1);
        Ep[p] = pack2(__expf(t0), (i1 < Tt) ? __expf(t1) : 0.f);
    }

    // ---- l = 0 ----
    const float* emp = em + (size_t)b * Tt + j;            // em[0][b][j]
    float e = act ? *emp : 0.f;
    emp += (size_t)Bf * Tt;
    float s0 = start[j] + e;
    float v = act ? s0 : -1e30f;
    float a = act ? __expf(s0) : 0.f;
    float* gsp = &g_score[(size_t)b * GST + j];
    if (act) *gsp = s0;
    gsp += (size_t)Bf * GST;

    // prefetch em[1]
    float en = act ? *emp : 0.f;
    emp += (size_t)Bf * Tt;

    float logacc = 0.f;

    for (int l = 1; l < Lf; l++) {
        e = en;
        if (l < Lf - 1) { en = act ? *emp : 0.f; emp += (size_t)Bf * Tt; }

        u64 r2 = 0ull;
        float m = -1e30f;
        float a0 = 0.f;
#pragma unroll
        for (int p = 0; p < NP; p++) {
            float ax = __shfl_sync(0xffffffffu, a, 2 * p);
            float ay = __shfl_sync(0xffffffffu, a, 2 * p + 1);
            float vx = __shfl_sync(0xffffffffu, v, 2 * p);
            float vy = __shfl_sync(0xffffffffu, v, 2 * p + 1);
            if (p == 0) a0 = ax;
            r2 = fma2(pack2(ax, ay), Ep[p], r2);
            float sx, sy; un2(add2(pack2(vx, vy), Tp[p]), sx, sy);
            m = fmaxf(m, fmaxf(sx, sy));
        }
        const float la = __logf(a0);
        logacc += la;

        float rx, ry; un2(r2, rx, ry);
        float u  = (rx + ry) * __expf(e - la);
        float sv = m + e;                   // == max_i((v+T)+e) exactly (monotone)
        a = act ? u  : 0.f;
        v = act ? sv : -1e30f;
        if (act) *gsp = sv;
        gsp += (size_t)Bf * GST;
    }

    // logz = sum log(scale) + log( sum_i a_final[i] * exp(end[i]) )
    float d = act ? a * __expf(endt[j]) : 0.f;
#pragma unroll
    for (int off = 16; off; off >>= 1) d += __shfl_xor_sync(0xffffffffu, d, off);
    if (lane == 0) g_logz[b] = logacc + __logf(d);
}

// ---------------------------------------------------------------------------
__global__ void numer_kernel(const float* __restrict__ em, const int* __restrict__ tags,
                             const float* __restrict__ trans, const float* __restrict__ start,
                             const float* __restrict__ endt)
{
    int idx = blockIdx.x * blockDim.x + threadIdx.x;
    if (idx >= Bf * 32) return;
    int b  = idx & (Bf - 1);
    int c  = idx >> 12;
    int l0 = c * 16;
    float acc = 0.f;
    int prev = 0;
    if (c > 0) prev = tags[(size_t)(l0 - 1) * Bf + b];
#pragma unroll
    for (int dl = 0; dl < 16; dl++) {
        int l  = l0 + dl;
        int tg = tags[(size_t)l * Bf + b];
        acc += em[((size_t)l * Bf + b) * Tt + tg];
        if (l == 0) acc += start[tg];
        else        acc += trans[prev * Tt + tg];
        prev = tg;
    }
    if (l0 + 16 == Lf) acc += endt[prev];
    atomicAdd(&g_num[b], acc);
}

// ---------------------------------------------------------------------------
// Backtrack group body: 8 steps with CONSTANT-INDEX register buffers,
// prefetching the next group's 16 loads (addresses are jn-independent).
__device__ __forceinline__ void bt_group(
    const float* __restrict__ em, const float* st, float* out, int base,
    int b, int lane, bool alive, int lbase, int& jn,
    float (&cs)[8], float (&ce)[8], float (&ns)[8], float (&ne)[8], bool load_next)
{
    if (load_next) {
#pragma unroll
        for (int k = 0; k < 8; k++) {
            int l = lbase - 8 - k;
            bool ok = alive && (l >= 0);
            ns[k] = ok ? g_score[((size_t)l * Bf + b) * GST + lane] : 0.f;
            ne[k] = ok ? em[((size_t)(l + 1) * Bf + b) * Tt + lane] : 0.f;
        }
    }
#pragma unroll
    for (int k = 0; k < 8; k++) {
        int l = lbase - k;
        float ej = __shfl_sync(0xffffffffu, ce[k], jn);
        float tt = alive ? (cs[k] + st[lane * Tt + jn]) + ej : -3e38f;
        unsigned uu = ford(tt);
        unsigned mx = __reduce_max_sync(0xffffffffu, uu);
        int j2 = __ffs(__ballot_sync(0xffffffffu, uu == mx)) - 1;
        if (l >= 0) {
            jn = j2;
            if (lane == 0) out[base + (size_t)l * Bf + b] = (float)jn;
        }
    }
}

__global__ __launch_bounds__(256) void backtrack_kernel(
    const float* __restrict__ em, const float* __restrict__ trans,
    const float* __restrict__ endt, float* __restrict__ out, int base)
{
    __shared__ float st[Tt * Tt];
    __shared__ float cpart[8];
    const int tid = threadIdx.x;
    for (int i = tid; i < Tt * Tt; i += 256) st[i] = trans[i];
    __syncthreads();

    const int b    = (blockIdx.x * 256 + tid) >> 5;
    const int lane = tid & 31;
    const bool alive = lane < Tt;

    float sc = alive ? g_score[((size_t)(Lf - 1) * Bf + b) * GST + lane] : -3e38f;
    float t  = alive ? sc + endt[lane] : -3e38f;
    unsigned u  = ford(t);
    unsigned um = __reduce_max_sync(0xffffffffu, u);
    int jn = __ffs(__ballot_sync(0xffffffffu, u == um)) - 1;
    if (lane == 0) out[base + (size_t)(Lf - 1) * Bf + b] = (float)jn;

    float sA[8], eA[8], sB[8], eB[8];
#pragma unroll
    for (int k = 0; k < 8; k++) {
        int l = Lf - 2 - k;
        sA[k] = alive ? g_score[((size_t)l * Bf + b) * GST + lane] : 0.f;
        eA[k] = alive ? em[((size_t)(l + 1) * Bf + b) * Tt + lane] : 0.f;
    }
    for (int g = 0; g < 64; g += 2) {
        bt_group(em, st, out, base, b, lane, alive, Lf - 2 - 8 * g, jn,
                 sA, eA, sB, eB, true);
        bt_group(em, st, out, base, b, lane, alive, Lf - 2 - 8 * (g + 1), jn,
                 sB, eB, sA, eA, g + 1 < 63);
    }

    float c = 0.f;
    if (lane == 0 && base > 0) c = (g_logz[b] - g_num[b]) * (1.0f / Bf);
    if (lane == 0) cpart[tid >> 5] = c;
    __syncthreads();
    if (tid == 0 && base > 0) {
        float sum = 0.f;
#pragma unroll
        for (int w = 0; w < 8; w++) sum += cpart[w];
        atomicAdd(out, sum);
    }
}

// ---------------------------------------------------------------------------
extern "C" void kernel_launch(void* const* d_in, const int* in_sizes, int n_in,
                              void* d_out, int out_size) {
    const float* em    = (const float*)d_in[0];
    const int*   tags  = (const int*)d_in[1];
    const float* trans = (const float*)d_in[2];
    const float* start = (const float*)d_in[3];
    const float* endt  = (const float*)d_in[4];
    float* out = (float*)d_out;

    int base = out_size - Lf * Bf;
    if (base < 0) base = 0;

    init_kernel<<<16, 256>>>(out, base);
    fwd_vit_kernel<<<Bf * 32 / 256, 256>>>(em, trans, start, endt);
    numer_kernel<<<(Bf * 32) / 256, 256>>>(em, tags, trans, start, endt);
    backtrack_kernel<<<(Bf * 32) / 256, 256>>>(em, trans, endt, out, base);
}

// round 7
// speedup vs baseline: 2.3209x; 1.2272x over previous
#include <cuda_runtime.h>

#define Lf 512
#define Bf 4096
#define Tt 25
#define NP 13      // i-pairs (2p, 2p+1); p=12 hi half = pad lane 25
#define GST 32     // g_score row stride (128B-aligned rows)

__device__ float g_score[(size_t)Lf * Bf * GST];
__device__ float g_logz[Bf];
__device__ float g_num[Bf];

typedef unsigned long long u64;

__device__ __forceinline__ u64 pack2(float lo, float hi) {
    u64 r; asm("mov.b64 %0,{%1,%2};" : "=l"(r) : "f"(lo), "f"(hi)); return r;
}
__device__ __forceinline__ void un2(u64 v, float& a, float& b) {
    asm("mov.b64 {%0,%1},%2;" : "=f"(a), "=f"(b) : "l"(v));
}
__device__ __forceinline__ u64 fma2(u64 a, u64 b, u64 c) {
    u64 d; asm("fma.rn.f32x2 %0,%1,%2,%3;" : "=l"(d) : "l"(a), "l"(b), "l"(c)); return d;
}
__device__ __forceinline__ u64 add2(u64 a, u64 b) {
    u64 d; asm("add.rn.f32x2 %0,%1,%2;" : "=l"(d) : "l"(a), "l"(b)); return d;
}
__device__ __forceinline__ unsigned ford(float f) {
    unsigned v = __float_as_uint(f);
    return (v & 0x80000000u) ? ~v : (v | 0x80000000u);
}

// ---------------------------------------------------------------------------
__global__ void init_kernel(float* out, int base) {
    int i = blockIdx.x * blockDim.x + threadIdx.x;
    if (i < Bf) g_num[i] = 0.f;
    if (i == 0 && base > 0) out[0] = 0.f;
}

// ---------------------------------------------------------------------------
// Fused forward + Viterbi: 2 chains per warp, warp-private smem state
// broadcast (STS.64 + 13x LDS.128 per chain per step), no block barriers.
// Forward in scaled linear space (normalized each step by previous alpha[0]).
__global__ __launch_bounds__(256, 2) void fwd_vit_kernel(
    const float* __restrict__ em, const float* __restrict__ trans,
    const float* __restrict__ start, const float* __restrict__ endt)
{
    // [warp][chain][buf][lane] : (a, v)
    __shared__ __align__(16) float2 sbuf[8][2][2][32];

    const int lane = threadIdx.x & 31;
    const int wl   = threadIdx.x >> 5;                 // warp in block
    const int w    = blockIdx.x * 8 + wl;              // 0..2047
    const int bA   = w;
    const int bB   = w + Bf / 2;
    const bool act = lane < Tt;
    const int  j   = act ? lane : 0;

    // loop-invariant tables: column j of exp(trans) / trans, packed over i-pairs
    u64 Ep[NP], Tp[NP];
#pragma unroll
    for (int p = 0; p < NP; p++) {
        const int i0 = 2 * p, i1 = 2 * p + 1;
        float t0 = trans[i0 * Tt + j];
        float t1 = (i1 < Tt) ? trans[i1 * Tt + j] : -1e30f;
        Tp[p] = pack2(t0, t1);
        Ep[p] = pack2(__expf(t0), (i1 < Tt) ? __expf(t1) : 0.f);
    }

    // ---- l = 0 ----
    const float* empA = em + (size_t)bA * Tt + j;
    const float* empB = em + (size_t)bB * Tt + j;
    const size_t emstep = (size_t)Bf * Tt;
    float eA = act ? *empA : 0.f;   empA += emstep;
    float eB = act ? *empB : 0.f;   empB += emstep;
    const float stj = start[j];
    float s0A = stj + eA, s0B = stj + eB;
    float vA = act ? s0A : -1e30f,  vB = act ? s0B : -1e30f;
    float aA = act ? __expf(s0A) : 0.f, aB = act ? __expf(s0B) : 0.f;

    float* gspA = &g_score[(size_t)bA * GST + j];
    float* gspB = &g_score[(size_t)bB * GST + j];
    const size_t gstep = (size_t)Bf * GST;
    if (act) { *gspA = s0A; *gspB = s0B; }
    gspA += gstep; gspB += gstep;

    // prefetch em[1]
    float enA = act ? *empA : 0.f;  empA += emstep;
    float enB = act ? *empB : 0.f;  empB += emstep;

    float logaccA = 0.f, logaccB = 0.f;

    for (int l = 1; l < Lf; l++) {
        eA = enA; eB = enB;
        if (l < Lf - 1) {
            enA = act ? *empA : 0.f; empA += emstep;
            enB = act ? *empB : 0.f; empB += emstep;
        }

        // publish previous state (step l-1) to this step's buffer
        const int bp = (l - 1) & 1;
        sbuf[wl][0][bp][lane] = make_float2(aA, vA);
        sbuf[wl][1][bp][lane] = make_float2(aB, vB);
        __syncwarp();

        const float4* pA = (const float4*)&sbuf[wl][0][bp][0];
        const float4* pB = (const float4*)&sbuf[wl][1][bp][0];

        u64 rA = 0ull, rB = 0ull;
        float mA0 = -1e30f, mA1 = -1e30f, mB0 = -1e30f, mB1 = -1e30f;
        float a0A = 0.f, a0B = 0.f;
#pragma unroll
        for (int p = 0; p < NP; p++) {
            float4 fA = pA[p];     // (a2p, v2p, a2p+1, v2p+1) broadcast
            float4 fB = pB[p];
            if (p == 0) { a0A = fA.x; a0B = fB.x; }
            rA = fma2(pack2(fA.x, fA.z), Ep[p], rA);
            rB = fma2(pack2(fB.x, fB.z), Ep[p], rB);
            float sx, sy;
            un2(add2(pack2(fA.y, fA.w), Tp[p]), sx, sy);
            mA0 = fmaxf(mA0, sx); mA1 = fmaxf(mA1, sy);
            un2(add2(pack2(fB.y, fB.w), Tp[p]), sx, sy);
            mB0 = fmaxf(mB0, sx); mB1 = fmaxf(mB1, sy);
        }
        const float laA = __logf(a0A);
        const float laB = __logf(a0B);
        logaccA += laA; logaccB += laB;

        float rx, ry;
        un2(rA, rx, ry); float uA = (rx + ry) * __expf(eA - laA);
        un2(rB, rx, ry); float uB = (rx + ry) * __expf(eB - laB);
        float svA = fmaxf(mA0, mA1) + eA;     // == max_i((v+T)+e) (monotone add)
        float svB = fmaxf(mB0, mB1) + eB;

        aA = act ? uA : 0.f;   vA = act ? svA : -1e30f;
        aB = act ? uB : 0.f;   vB = act ? svB : -1e30f;
        if (act) { *gspA = svA; *gspB = svB; }
        gspA += gstep; gspB += gstep;
    }

    // logz = sum log(scale) + log( sum_i a_final[i] * exp(end[i]) )
    float ee = __expf(endt[j]);
    float dA = act ? aA * ee : 0.f;
    float dB = act ? aB * ee : 0.f;
#pragma unroll
    for (int off = 16; off; off >>= 1) {
        dA += __shfl_xor_sync(0xffffffffu, dA, off);
        dB += __shfl_xor_sync(0xffffffffu, dB, off);
    }
    if (lane == 0) {
        g_logz[bA] = logaccA + __logf(dA);
        g_logz[bB] = logaccB + __logf(dB);
    }
}

// ---------------------------------------------------------------------------
__global__ void numer_kernel(const float* __restrict__ em, const int* __restrict__ tags,
                             const float* __restrict__ trans, const float* __restrict__ start,
                             const float* __restrict__ endt)
{
    int idx = blockIdx.x * blockDim.x + threadIdx.x;
    if (idx >= Bf * 32) return;
    int b  = idx & (Bf - 1);
    int c  = idx >> 12;
    int l0 = c * 16;
    float acc = 0.f;
    int prev = 0;
    if (c > 0) prev = tags[(size_t)(l0 - 1) * Bf + b];
#pragma unroll
    for (int dl = 0; dl < 16; dl++) {
        int l  = l0 + dl;
        int tg = tags[(size_t)l * Bf + b];
        acc += em[((size_t)l * Bf + b) * Tt + tg];
        if (l == 0) acc += start[tg];
        else        acc += trans[prev * Tt + tg];
        prev = tg;
    }
    if (l0 + 16 == Lf) acc += endt[prev];
    atomicAdd(&g_num[b], acc);
}

// ---------------------------------------------------------------------------
// Backtrack group body: 8 steps with CONSTANT-INDEX register buffers,
// prefetching the next group's 16 loads (addresses are jn-independent).
__device__ __forceinline__ void bt_group(
    const float* __restrict__ em, const float* st, float* out, int base,
    int b, int lane, bool alive, int lbase, int& jn,
    float (&cs)[8], float (&ce)[8], float (&ns)[8], float (&ne)[8], bool load_next)
{
    if (load_next) {
#pragma unroll
        for (int k = 0; k < 8; k++) {
            int l = lbase - 8 - k;
            bool ok = alive && (l >= 0);
            ns[k] = ok ? g_score[((size_t)l * Bf + b) * GST + lane] : 0.f;
            ne[k] = ok ? em[((size_t)(l + 1) * Bf + b) * Tt + lane] : 0.f;
        }
    }
#pragma unroll
    for (int k = 0; k < 8; k++) {
        int l = lbase - k;
        float ej = __shfl_sync(0xffffffffu, ce[k], jn);
        float tt = alive ? (cs[k] + st[lane * Tt + jn]) + ej : -3e38f;
        unsigned uu = ford(tt);
        unsigned mx = __reduce_max_sync(0xffffffffu, uu);
        int j2 = __ffs(__ballot_sync(0xffffffffu, uu == mx)) - 1;
        if (l >= 0) {
            jn = j2;
            if (lane == 0) out[base + (size_t)l * Bf + b] = (float)jn;
        }
    }
}

__global__ __launch_bounds__(256) void backtrack_kernel(
    const float* __restrict__ em, const float* __restrict__ trans,
    const float* __restrict__ endt, float* __restrict__ out, int base)
{
    __shared__ float st[Tt * Tt];
    __shared__ float cpart[8];
    const int tid = threadIdx.x;
    for (int i = tid; i < Tt * Tt; i += 256) st[i] = trans[i];
    __syncthreads();

    const int b    = (blockIdx.x * 256 + tid) >> 5;
    const int lane = tid & 31;
    const bool alive = lane < Tt;

    float sc = alive ? g_score[((size_t)(Lf - 1) * Bf + b) * GST + lane] : -3e38f;
    float t  = alive ? sc + endt[lane] : -3e38f;
    unsigned u  = ford(t);
    unsigned um = __reduce_max_sync(0xffffffffu, u);
    int jn = __ffs(__ballot_sync(0xffffffffu, u == um)) - 1;
    if (lane == 0) out[base + (size_t)(Lf - 1) * Bf + b] = (float)jn;

    float sA[8], eA[8], sB[8], eB[8];
#pragma unroll
    for (int k = 0; k < 8; k++) {
        int l = Lf - 2 - k;
        sA[k] = alive ? g_score[((size_t)l * Bf + b) * GST + lane] : 0.f;
        eA[k] = alive ? em[((size_t)(l + 1) * Bf + b) * Tt + lane] : 0.f;
    }
    for (int g = 0; g < 64; g += 2) {
        bt_group(em, st, out, base, b, lane, alive, Lf - 2 - 8 * g, jn,
                 sA, eA, sB, eB, true);
        bt_group(em, st, out, base, b, lane, alive, Lf - 2 - 8 * (g + 1), jn,
                 sB, eB, sA, eA, g + 1 < 63);
    }

    float c = 0.f;
    if (lane == 0 && base > 0) c = (g_logz[b] - g_num[b]) * (1.0f / Bf);
    if (lane == 0) cpart[tid >> 5] = c;
    __syncthreads();
    if (tid == 0 && base > 0) {
        float sum = 0.f;
#pragma unroll
        for (int w = 0; w < 8; w++) sum += cpart[w];
        atomicAdd(out, sum);
    }
}

// ---------------------------------------------------------------------------
extern "C" void kernel_launch(void* const* d_in, const int* in_sizes, int n_in,
                              void* d_out, int out_size) {
    const float* em    = (const float*)d_in[0];
    const int*   tags  = (const int*)d_in[1];
    const float* trans = (const float*)d_in[2];
    const float* start = (const float*)d_in[3];
    const float* endt  = (const float*)d_in[4];
    float* out = (float*)d_out;

    int base = out_size - Lf * Bf;
    if (base < 0) base = 0;

    init_kernel<<<16, 256>>>(out, base);
    fwd_vit_kernel<<<Bf / 16, 256>>>(em, trans, start, endt);   // 256 blocks, 1 wave
    numer_kernel<<<(Bf * 32) / 256, 256>>>(em, tags, trans, start, endt);
    backtrack_kernel<<<(Bf * 32) / 256, 256>>>(em, trans, endt, out, base);
}

// round 8
// speedup vs baseline: 2.3318x; 1.0047x over previous
#include <cuda_runtime.h>

#define Lf 512
#define Bf 4096
#define Tt 25
#define NP 13      // i-pairs (2p, 2p+1); slot p=12 hi half = pad (i=25)
#define GST 32     // g_score row stride (128B-aligned rows)

__device__ float g_score[(size_t)Lf * Bf * GST];
__device__ float g_logz[Bf];
__device__ float g_num[Bf];

typedef unsigned long long u64;

__device__ __forceinline__ u64 pack2(float lo, float hi) {
    u64 r; asm("mov.b64 %0,{%1,%2};" : "=l"(r) : "f"(lo), "f"(hi)); return r;
}
__device__ __forceinline__ void un2(u64 v, float& a, float& b) {
    asm("mov.b64 {%0,%1},%2;" : "=f"(a), "=f"(b) : "l"(v));
}
__device__ __forceinline__ u64 fma2(u64 a, u64 b, u64 c) {
    u64 d; asm("fma.rn.f32x2 %0,%1,%2,%3;" : "=l"(d) : "l"(a), "l"(b), "l"(c)); return d;
}
__device__ __forceinline__ u64 add2(u64 a, u64 b) {
    u64 d; asm("add.rn.f32x2 %0,%1,%2;" : "=l"(d) : "l"(a), "l"(b)); return d;
}
__device__ __forceinline__ unsigned ford(float f) {
    unsigned v = __float_as_uint(f);
    return (v & 0x80000000u) ? ~v : (v | 0x80000000u);
}

// ---------------------------------------------------------------------------
__global__ void init_kernel(float* out, int base) {
    int i = blockIdx.x * blockDim.x + threadIdx.x;
    if (i < Bf) g_num[i] = 0.f;
    if (i == 0 && base > 0) out[0] = 0.f;
}

// ---------------------------------------------------------------------------
// Fused forward + Viterbi: 2 chains per warp. State kept in smem in packed
// i-pair layout {a2p, a2p+1, v2p, v2p+1} so the consumer LDS.128 feeds
// fma.rn.f32x2 / add.rn.f32x2 directly (no repacking MOVs).
__global__ __launch_bounds__(256, 2) void fwd_vit_kernel(
    const float* __restrict__ em, const float* __restrict__ trans,
    const float* __restrict__ start, const float* __restrict__ endt)
{
    // [buf][warp][chain][pair][4 floats: a_lo, a_hi, v_lo, v_hi]
    __shared__ __align__(16) float sst[2][8][2][NP][4];

    const int lane = threadIdx.x & 31;
    const int wl   = threadIdx.x >> 5;
    const int w    = blockIdx.x * 8 + wl;              // 0..2047
    const int bA   = w;
    const int bB   = w + Bf / 2;
    const bool act = lane < Tt;
    const int  j   = act ? lane : 0;
    const int  sp  = lane >> 1;                        // state slot
    const int  sh  = lane & 1;                         // half within pair
    const bool wr  = lane < 26;                        // state writers (25 = pad)

    // loop-invariant tables
    u64 Ep[NP], Tp[NP];
#pragma unroll
    for (int p = 0; p < NP; p++) {
        const int i0 = 2 * p, i1 = 2 * p + 1;
        float t0 = trans[i0 * Tt + j];
        float t1 = (i1 < Tt) ? trans[i1 * Tt + j] : -1e30f;
        Tp[p] = pack2(t0, t1);
        Ep[p] = pack2(__expf(t0), (i1 < Tt) ? __expf(t1) : 0.f);
    }

    // ---- l = 0 ----
    const float* empA = em + (size_t)bA * Tt + j;
    const float* empB = em + (size_t)bB * Tt + j;
    const size_t emstep = (size_t)Bf * Tt;
    float eA = act ? *empA : 0.f;   empA += emstep;
    float eB = act ? *empB : 0.f;   empB += emstep;
    const float stj = start[j];
    float s0A = stj + eA, s0B = stj + eB;
    float vA = act ? s0A : -1e30f,  vB = act ? s0B : -1e30f;
    float aA = act ? __expf(s0A) : 0.f, aB = act ? __expf(s0B) : 0.f;

    float* gspA = &g_score[(size_t)bA * GST + j];
    float* gspB = &g_score[(size_t)bB * GST + j];
    const size_t gstep = (size_t)Bf * GST;
    if (act) { *gspA = s0A; *gspB = s0B; }
    gspA += gstep; gspB += gstep;

    float enA = act ? *empA : 0.f;  empA += emstep;
    float enB = act ? *empB : 0.f;  empB += emstep;

    float logaccA = 0.f, logaccB = 0.f;

    for (int l = 1; l < Lf; l++) {
        // publish state of step l-1 in packed layout
        const int bp = (l - 1) & 1;
        if (wr) {
            float* dA = &sst[bp][wl][0][sp][0];
            float* dB = &sst[bp][wl][1][sp][0];
            dA[sh] = aA;  dA[2 + sh] = vA;
            dB[sh] = aB;  dB[2 + sh] = vB;
        }
        __syncwarp();

        float e_A = enA, e_B = enB;
        if (l < Lf - 1) {
            enA = act ? *empA : 0.f; empA += emstep;
            enB = act ? *empB : 0.f; empB += emstep;
        }

        const ulonglong2* pA = (const ulonglong2*)&sst[bp][wl][0][0][0];
        const ulonglong2* pB = (const ulonglong2*)&sst[bp][wl][1][0][0];

        u64 rA = 0ull, rB = 0ull;
        float mA0 = -1e30f, mA1 = -1e30f, mB0 = -1e30f, mB1 = -1e30f;
        float a0A = 0.f, a0B = 0.f;
#pragma unroll
        for (int p = 0; p < NP; p++) {
            ulonglong2 sA2 = pA[p];     // .x = a-pair, .y = v-pair (broadcast)
            ulonglong2 sB2 = pB[p];
            if (p == 0) {
                float hx, hy;
                un2(sA2.x, a0A, hx);
                un2(sB2.x, a0B, hy);
            }
            rA = fma2(sA2.x, Ep[p], rA);
            rB = fma2(sB2.x, Ep[p], rB);
            float sx, sy;
            un2(add2(sA2.y, Tp[p]), sx, sy);
            mA0 = fmaxf(mA0, sx); mA1 = fmaxf(mA1, sy);
            un2(add2(sB2.y, Tp[p]), sx, sy);
            mB0 = fmaxf(mB0, sx); mB1 = fmaxf(mB1, sy);
        }
        const float laA = __logf(a0A);
        const float laB = __logf(a0B);
        logaccA += laA; logaccB += laB;

        float rx, ry;
        un2(rA, rx, ry); float uA = (rx + ry) * __expf(e_A - laA);
        un2(rB, rx, ry); float uB = (rx + ry) * __expf(e_B - laB);
        float svA = fmaxf(mA0, mA1) + e_A;    // == max_i((v+T)+e) (monotone add)
        float svB = fmaxf(mB0, mB1) + e_B;

        aA = act ? uA : 0.f;   vA = act ? svA : -1e30f;
        aB = act ? uB : 0.f;   vB = act ? svB : -1e30f;
        if (act) { *gspA = svA; *gspB = svB; }
        gspA += gstep; gspB += gstep;
    }

    // logz = sum log(scale) + log( sum_i a_final[i] * exp(end[i]) )
    float ee = __expf(endt[j]);
    float dA = act ? aA * ee : 0.f;
    float dB = act ? aB * ee : 0.f;
#pragma unroll
    for (int off = 16; off; off >>= 1) {
        dA += __shfl_xor_sync(0xffffffffu, dA, off);
        dB += __shfl_xor_sync(0xffffffffu, dB, off);
    }
    if (lane == 0) {
        g_logz[bA] = logaccA + __logf(dA);
        g_logz[bB] = logaccB + __logf(dB);
    }
}

// ---------------------------------------------------------------------------
__global__ void numer_kernel(const float* __restrict__ em, const int* __restrict__ tags,
                             const float* __restrict__ trans, const float* __restrict__ start,
                             const float* __restrict__ endt)
{
    int idx = blockIdx.x * blockDim.x + threadIdx.x;
    if (idx >= Bf * 32) return;
    int b  = idx & (Bf - 1);
    int c  = idx >> 12;
    int l0 = c * 16;
    float acc = 0.f;
    int prev = 0;
    if (c > 0) prev = tags[(size_t)(l0 - 1) * Bf + b];
#pragma unroll
    for (int dl = 0; dl < 16; dl++) {
        int l  = l0 + dl;
        int tg = tags[(size_t)l * Bf + b];
        acc += em[((size_t)l * Bf + b) * Tt + tg];
        if (l == 0) acc += start[tg];
        else        acc += trans[prev * Tt + tg];
        prev = tg;
    }
    if (l0 + 16 == Lf) acc += endt[prev];
    atomicAdd(&g_num[b], acc);
}

// ---------------------------------------------------------------------------
__device__ __forceinline__ void bt_group(
    const float* __restrict__ em, const float* st, float* out, int base,
    int b, int lane, bool alive, int lbase, int& jn,
    float (&cs)[8], float (&ce)[8], float (&ns)[8], float (&ne)[8], bool load_next)
{
    if (load_next) {
#pragma unroll
        for (int k = 0; k < 8; k++) {
            int l = lbase - 8 - k;
            bool ok = alive && (l >= 0);
            ns[k] = ok ? g_score[((size_t)l * Bf + b) * GST + lane] : 0.f;
            ne[k] = ok ? em[((size_t)(l + 1) * Bf + b) * Tt + lane] : 0.f;
        }
    }
#pragma unroll
    for (int k = 0; k < 8; k++) {
        int l = lbase - k;
        float ej = __shfl_sync(0xffffffffu, ce[k], jn);
        float tt = alive ? (cs[k] + st[lane * Tt + jn]) + ej : -3e38f;
        unsigned uu = ford(tt);
        unsigned mx = __reduce_max_sync(0xffffffffu, uu);
        int j2 = __ffs(__ballot_sync(0xffffffffu, uu == mx)) - 1;
        if (l >= 0) {
            jn = j2;
            if (lane == 0) out[base + (size_t)l * Bf + b] = (float)jn;
        }
    }
}

__global__ __launch_bounds__(256) void backtrack_kernel(
    const float* __restrict__ em, const float* __restrict__ trans,
    const float* __restrict__ endt, float* __restrict__ out, int base)
{
    __shared__ float st[Tt * Tt];
    __shared__ float cpart[8];
    const int tid = threadIdx.x;
    for (int i = tid; i < Tt * Tt; i += 256) st[i] = trans[i];
    __syncthreads();

    const int b    = (blockIdx.x * 256 + tid) >> 5;
    const int lane = tid & 31;
    const bool alive = lane < Tt;

    float sc = alive ? g_score[((size_t)(Lf - 1) * Bf + b) * GST + lane] : -3e38f;
    float t  = alive ? sc + endt[lane] : -3e38f;
    unsigned u  = ford(t);
    unsigned um = __reduce_max_sync(0xffffffffu, u);
    int jn = __ffs(__ballot_sync(0xffffffffu, u == um)) - 1;
    if (lane == 0) out[base + (size_t)(Lf - 1) * Bf + b] = (float)jn;

    float sA[8], eA[8], sB[8], eB[8];
#pragma unroll
    for (int k = 0; k < 8; k++) {
        int l = Lf - 2 - k;
        sA[k] = alive ? g_score[((size_t)l * Bf + b) * GST + lane] : 0.f;
        eA[k] = alive ? em[((size_t)(l + 1) * Bf + b) * Tt + lane] : 0.f;
    }
    for (int g = 0; g < 64; g += 2) {
        bt_group(em, st, out, base, b, lane, alive, Lf - 2 - 8 * g, jn,
                 sA, eA, sB, eB, true);
        bt_group(em, st, out, base, b, lane, alive, Lf - 2 - 8 * (g + 1), jn,
                 sB, eB, sA, eA, g + 1 < 63);
    }

    float c = 0.f;
    if (lane == 0 && base > 0) c = (g_logz[b] - g_num[b]) * (1.0f / Bf);
    if (lane == 0) cpart[tid >> 5] = c;
    __syncthreads();
    if (tid == 0 && base > 0) {
        float sum = 0.f;
#pragma unroll
        for (int w = 0; w < 8; w++) sum += cpart[w];
        atomicAdd(out, sum);
    }
}

// ---------------------------------------------------------------------------
extern "C" void kernel_launch(void* const* d_in, const int* in_sizes, int n_in,
                              void* d_out, int out_size) {
    const float* em    = (const float*)d_in[0];
    const int*   tags  = (const int*)d_in[1];
    const float* trans = (const float*)d_in[2];
    const float* start = (const float*)d_in[3];
    const float* endt  = (const float*)d_in[4];
    float* out = (float*)d_out;

    int base = out_size - Lf * Bf;
    if (base < 0) base = 0;

    init_kernel<<<16, 256>>>(out, base);
    fwd_vit_kernel<<<Bf / 16, 256>>>(em, trans, start, endt);   // 256 blocks, 1 wave
    numer_kernel<<<(Bf * 32) / 256, 256>>>(em, tags, trans, start, endt);
    backtrack_kernel<<<(Bf * 32) / 256, 256>>>(em, trans, endt, out, base);
}